// round 2
// baseline (speedup 1.0000x reference)
#include <cuda_runtime.h>
#include <cuda_bf16.h>
#include <cstdint>

#define NUM_NETS_MAX 2000000

// Per-net accumulators: {exp(+x/g), exp(-x/g), exp(+y/g), exp(-y/g)}
__device__ float4 g_net_sums[NUM_NETS_MAX];

// ---------------------------------------------------------------------------
// Kernel 1: zero scratch + output (graph is replayed, so re-zero every launch)
// ---------------------------------------------------------------------------
__global__ void zero_kernel(float* __restrict__ out, int num_nets) {
    int i = blockIdx.x * blockDim.x + threadIdx.x;
    if (i < num_nets) {
        g_net_sums[i] = make_float4(0.f, 0.f, 0.f, 0.f);
    }
    if (i == 0) {
        *out = 0.f;
    }
}

// ---------------------------------------------------------------------------
// Kernel 2: per-pin exp + scatter-add. 4 pins per thread via vector loads.
// ---------------------------------------------------------------------------
__device__ __forceinline__ void scatter_pin(float sx, float sy, int net) {
    float epx = __expf(sx);
    float enx = __expf(-sx);
    float epy = __expf(sy);
    float eny = __expf(-sy);
    float* base = reinterpret_cast<float*>(&g_net_sums[net]);
    asm volatile("red.global.add.v2.f32 [%0], {%1, %2};"
                 :: "l"(base), "f"(epx), "f"(enx) : "memory");
    asm volatile("red.global.add.v2.f32 [%0], {%1, %2};"
                 :: "l"(base + 2), "f"(epy), "f"(eny) : "memory");
}

__global__ void __launch_bounds__(256) pins_kernel_vec4(
    const float4* __restrict__ posx,
    const float4* __restrict__ posy,
    const int4*   __restrict__ pin2net,
    const float*  __restrict__ gamma_ptr,
    int num_quads)
{
    int q = blockIdx.x * blockDim.x + threadIdx.x;
    if (q >= num_quads) return;

    float inv_g = 1.0f / (*gamma_ptr);

    float4 px = posx[q];
    float4 py = posy[q];
    int4   nn = pin2net[q];

    scatter_pin(px.x * inv_g, py.x * inv_g, nn.x);
    scatter_pin(px.y * inv_g, py.y * inv_g, nn.y);
    scatter_pin(px.z * inv_g, py.z * inv_g, nn.z);
    scatter_pin(px.w * inv_g, py.w * inv_g, nn.w);
}

// Tail kernel for num_pins % 4 != 0 (not needed for 10M but keep it correct).
__global__ void pins_kernel_tail(
    const float* __restrict__ pos,
    const int*   __restrict__ pin2net,
    const float* __restrict__ gamma_ptr,
    int start, int num_pins)
{
    int p = start + blockIdx.x * blockDim.x + threadIdx.x;
    if (p >= num_pins) return;
    float inv_g = 1.0f / (*gamma_ptr);
    scatter_pin(pos[p] * inv_g, pos[p + num_pins] * inv_g, pin2net[p]);
}

// ---------------------------------------------------------------------------
// Kernel 3: per-net log + masked global reduction.
// net_mask is int32 on device (JAX bool -> i32 materialization).
// ---------------------------------------------------------------------------
__global__ void __launch_bounds__(256) nets_kernel(
    const int*   __restrict__ net_mask,
    const float* __restrict__ gamma_ptr,
    float* __restrict__ out,
    int num_nets)
{
    int n = blockIdx.x * blockDim.x + threadIdx.x;

    float v = 0.f;
    if (n < num_nets && net_mask[n] != 0) {
        float4 s = g_net_sums[n];
        float g = *gamma_ptr;
        float lpx = (s.x > 0.f) ? __logf(s.x) : 0.f;
        float lnx = (s.y > 0.f) ? __logf(s.y) : 0.f;
        float lpy = (s.z > 0.f) ? __logf(s.z) : 0.f;
        float lny = (s.w > 0.f) ? __logf(s.w) : 0.f;
        v = g * ((lpx + lnx) + (lpy + lny));
    }

    // warp reduce
    #pragma unroll
    for (int o = 16; o > 0; o >>= 1)
        v += __shfl_down_sync(0xFFFFFFFFu, v, o);

    __shared__ float sh[8];  // 256 threads = 8 warps
    int lane = threadIdx.x & 31;
    int wid  = threadIdx.x >> 5;
    if (lane == 0) sh[wid] = v;
    __syncthreads();

    if (wid == 0) {
        float bv = (lane < 8) ? sh[lane] : 0.f;
        #pragma unroll
        for (int o = 4; o > 0; o >>= 1)
            bv += __shfl_down_sync(0xFFFFFFFFu, bv, o);
        if (lane == 0)
            atomicAdd(out, bv);
    }
}

// ---------------------------------------------------------------------------
extern "C" void kernel_launch(void* const* d_in, const int* in_sizes, int n_in,
                              void* d_out, int out_size)
{
    const float* pos       = (const float*)d_in[0];   // [2 * num_pins]
    const int*   pin2net   = (const int*)d_in[1];     // [num_pins]
    const int*   net_mask  = (const int*)d_in[2];     // [num_nets] (bool as i32)
    const float* gamma_ptr = (const float*)d_in[3];   // scalar

    int num_pins = in_sizes[0] / 2;
    int num_nets = in_sizes[2];
    float* out = (float*)d_out;

    const int T = 256;
    int zb = (num_nets + T - 1) / T;
    int nb = (num_nets + T - 1) / T;

    zero_kernel<<<zb, T>>>(out, num_nets);

    int num_quads = num_pins / 4;
    if (num_quads > 0) {
        int pb = (num_quads + T - 1) / T;
        pins_kernel_vec4<<<pb, T>>>(
            (const float4*)pos,
            (const float4*)(pos + num_pins),
            (const int4*)pin2net,
            gamma_ptr, num_quads);
    }
    int tail_start = num_quads * 4;
    if (tail_start < num_pins) {
        int tcount = num_pins - tail_start;
        pins_kernel_tail<<<(tcount + T - 1) / T, T>>>(
            pos, pin2net, gamma_ptr, tail_start, num_pins);
    }

    nets_kernel<<<nb, T>>>(net_mask, gamma_ptr, out, num_nets);
}

// round 3
// speedup vs baseline: 1.1596x; 1.1596x over previous
#include <cuda_runtime.h>
#include <cuda_bf16.h>
#include <cstdint>

#define NUM_NETS_MAX 2000000

// Per-net accumulators: {exp(+x/g), exp(-x/g), exp(+y/g), exp(-y/g)}
// Zero-initialized at module load; nets_kernel re-zeroes after consuming,
// so every kernel_launch (and every graph replay) starts from zeros.
__device__ float4 g_net_sums[NUM_NETS_MAX];

// ---------------------------------------------------------------------------
// Kernel 1: zero just the scalar output (tiny).
// ---------------------------------------------------------------------------
__global__ void zero_out_kernel(float* __restrict__ out) {
    *out = 0.f;
}

// ---------------------------------------------------------------------------
// Kernel 2: per-pin exp + scatter-add. 4 pins per thread via vector loads,
// ONE red.global.add.v4.f32 per pin (all 4 accumulator components at once).
// ---------------------------------------------------------------------------
__device__ __forceinline__ void scatter_pin(float sx, float sy, int net) {
    float epx = __expf(sx);
    float enx = __expf(-sx);
    float epy = __expf(sy);
    float eny = __expf(-sy);
    float* base = reinterpret_cast<float*>(&g_net_sums[net]);
    asm volatile("red.global.add.v4.f32 [%0], {%1, %2, %3, %4};"
                 :: "l"(base), "f"(epx), "f"(enx), "f"(epy), "f"(eny)
                 : "memory");
}

__global__ void __launch_bounds__(256) pins_kernel_vec4(
    const float4* __restrict__ posx,
    const float4* __restrict__ posy,
    const int4*   __restrict__ pin2net,
    const float*  __restrict__ gamma_ptr,
    int num_quads)
{
    int q = blockIdx.x * blockDim.x + threadIdx.x;
    if (q >= num_quads) return;

    float inv_g = 1.0f / (*gamma_ptr);

    float4 px = posx[q];
    float4 py = posy[q];
    int4   nn = pin2net[q];

    scatter_pin(px.x * inv_g, py.x * inv_g, nn.x);
    scatter_pin(px.y * inv_g, py.y * inv_g, nn.y);
    scatter_pin(px.z * inv_g, py.z * inv_g, nn.z);
    scatter_pin(px.w * inv_g, py.w * inv_g, nn.w);
}

// Tail kernel for num_pins % 4 != 0 (10M % 4 == 0, but stay correct).
__global__ void pins_kernel_tail(
    const float* __restrict__ pos,
    const int*   __restrict__ pin2net,
    const float* __restrict__ gamma_ptr,
    int start, int num_pins)
{
    int p = start + blockIdx.x * blockDim.x + threadIdx.x;
    if (p >= num_pins) return;
    float inv_g = 1.0f / (*gamma_ptr);
    scatter_pin(pos[p] * inv_g, pos[p + num_pins] * inv_g, pin2net[p]);
}

// ---------------------------------------------------------------------------
// Kernel 3: per-net log + masked global reduction. Also re-zeroes the
// accumulator slot after reading it (keeps scratch clean for next replay).
// net_mask is int32 on device (JAX bool -> i32 materialization).
// ---------------------------------------------------------------------------
__global__ void __launch_bounds__(256) nets_kernel(
    const int*   __restrict__ net_mask,
    const float* __restrict__ gamma_ptr,
    float* __restrict__ out,
    int num_nets)
{
    int n = blockIdx.x * blockDim.x + threadIdx.x;

    float v = 0.f;
    if (n < num_nets) {
        float4 s = g_net_sums[n];
        g_net_sums[n] = make_float4(0.f, 0.f, 0.f, 0.f);  // reset for next launch
        if (net_mask[n] != 0) {
            float g = *gamma_ptr;
            float lpx = (s.x > 0.f) ? __logf(s.x) : 0.f;
            float lnx = (s.y > 0.f) ? __logf(s.y) : 0.f;
            float lpy = (s.z > 0.f) ? __logf(s.z) : 0.f;
            float lny = (s.w > 0.f) ? __logf(s.w) : 0.f;
            v = g * ((lpx + lnx) + (lpy + lny));
        }
    }

    // warp reduce
    #pragma unroll
    for (int o = 16; o > 0; o >>= 1)
        v += __shfl_down_sync(0xFFFFFFFFu, v, o);

    __shared__ float sh[8];  // 256 threads = 8 warps
    int lane = threadIdx.x & 31;
    int wid  = threadIdx.x >> 5;
    if (lane == 0) sh[wid] = v;
    __syncthreads();

    if (wid == 0) {
        float bv = (lane < 8) ? sh[lane] : 0.f;
        #pragma unroll
        for (int o = 4; o > 0; o >>= 1)
            bv += __shfl_down_sync(0xFFFFFFFFu, bv, o);
        if (lane == 0)
            atomicAdd(out, bv);
    }
}

// ---------------------------------------------------------------------------
extern "C" void kernel_launch(void* const* d_in, const int* in_sizes, int n_in,
                              void* d_out, int out_size)
{
    const float* pos       = (const float*)d_in[0];   // [2 * num_pins]
    const int*   pin2net   = (const int*)d_in[1];     // [num_pins]
    const int*   net_mask  = (const int*)d_in[2];     // [num_nets] (bool as i32)
    const float* gamma_ptr = (const float*)d_in[3];   // scalar

    int num_pins = in_sizes[0] / 2;
    int num_nets = in_sizes[2];
    float* out = (float*)d_out;

    const int T = 256;

    zero_out_kernel<<<1, 1>>>(out);

    int num_quads = num_pins / 4;
    if (num_quads > 0) {
        int pb = (num_quads + T - 1) / T;
        pins_kernel_vec4<<<pb, T>>>(
            (const float4*)pos,
            (const float4*)(pos + num_pins),
            (const int4*)pin2net,
            gamma_ptr, num_quads);
    }
    int tail_start = num_quads * 4;
    if (tail_start < num_pins) {
        int tcount = num_pins - tail_start;
        pins_kernel_tail<<<(tcount + T - 1) / T, T>>>(
            pos, pin2net, gamma_ptr, tail_start, num_pins);
    }

    int nb = (num_nets + T - 1) / T;
    nets_kernel<<<nb, T>>>(net_mask, gamma_ptr, out, num_nets);
}

// round 4
// speedup vs baseline: 1.1981x; 1.0332x over previous
#include <cuda_runtime.h>
#include <cuda_fp16.h>
#include <cuda_bf16.h>
#include <cstdint>

#define NUM_NETS_MAX 2000000

// Per-net accumulators packed as 2x f16x2 in 8 bytes:
//   .x = half2{exp(+x/g), exp(-x/g)}, .y = half2{exp(+y/g), exp(-y/g)}
// Zero at module load; nets_kernel re-zeroes after consuming each slot so
// every launch / graph replay starts from zeros.
__device__ uint2 g_net_sums_h[NUM_NETS_MAX];

// ---------------------------------------------------------------------------
// Kernel 1 (fallback only): zero scalar output.
// ---------------------------------------------------------------------------
__global__ void zero_out_kernel(float* __restrict__ out) {
    *out = 0.f;
}

// ---------------------------------------------------------------------------
// Kernel 2: per-pin exp + scatter-add. 4 pins per thread via vector loads,
// ONE red.global.add.noftz.v2.f16x2 (8 bytes) per pin.
// ---------------------------------------------------------------------------
__device__ __forceinline__ void scatter_pin(float sx, float sy, int net) {
    float epx = __expf(sx);
    float enx = __expf(-sx);
    float epy = __expf(sy);
    float eny = __expf(-sy);
    __half2 hx = __floats2half2_rn(epx, enx);
    __half2 hy = __floats2half2_rn(epy, eny);
    unsigned rx = *reinterpret_cast<unsigned*>(&hx);
    unsigned ry = *reinterpret_cast<unsigned*>(&hy);
    asm volatile("red.global.add.noftz.v2.f16x2 [%0], {%1, %2};"
                 :: "l"(&g_net_sums_h[net]), "r"(rx), "r"(ry)
                 : "memory");
}

__global__ void __launch_bounds__(256) pins_kernel_vec4(
    const float4* __restrict__ posx,
    const float4* __restrict__ posy,
    const int4*   __restrict__ pin2net,
    const float*  __restrict__ gamma_ptr,
    float* __restrict__ out,
    int num_quads)
{
    int q = blockIdx.x * blockDim.x + threadIdx.x;
    if (q == 0) *out = 0.f;   // nets_kernel (later in stream) accumulates into it
    if (q >= num_quads) return;

    float inv_g = 1.0f / (*gamma_ptr);

    float4 px = posx[q];
    float4 py = posy[q];
    int4   nn = pin2net[q];

    scatter_pin(px.x * inv_g, py.x * inv_g, nn.x);
    scatter_pin(px.y * inv_g, py.y * inv_g, nn.y);
    scatter_pin(px.z * inv_g, py.z * inv_g, nn.z);
    scatter_pin(px.w * inv_g, py.w * inv_g, nn.w);
}

// Tail kernel for num_pins % 4 != 0 (10M % 4 == 0, but stay correct).
__global__ void pins_kernel_tail(
    const float* __restrict__ pos,
    const int*   __restrict__ pin2net,
    const float* __restrict__ gamma_ptr,
    int start, int num_pins)
{
    int p = start + blockIdx.x * blockDim.x + threadIdx.x;
    if (p >= num_pins) return;
    float inv_g = 1.0f / (*gamma_ptr);
    scatter_pin(pos[p] * inv_g, pos[p + num_pins] * inv_g, pin2net[p]);
}

// ---------------------------------------------------------------------------
// Kernel 3: per-net log + masked global reduction. Re-zeroes each slot after
// reading it. net_mask is int32 on device (JAX bool -> i32 materialization).
// ---------------------------------------------------------------------------
__global__ void __launch_bounds__(256) nets_kernel(
    const int*   __restrict__ net_mask,
    const float* __restrict__ gamma_ptr,
    float* __restrict__ out,
    int num_nets)
{
    int n = blockIdx.x * blockDim.x + threadIdx.x;

    float v = 0.f;
    if (n < num_nets) {
        uint2 raw = g_net_sums_h[n];
        g_net_sums_h[n] = make_uint2(0u, 0u);  // reset for next launch
        if (net_mask[n] != 0) {
            __half2 hx = *reinterpret_cast<__half2*>(&raw.x);
            __half2 hy = *reinterpret_cast<__half2*>(&raw.y);
            float spx = __low2float(hx);
            float snx = __high2float(hx);
            float spy = __low2float(hy);
            float sny = __high2float(hy);
            float g = *gamma_ptr;
            float lpx = (spx > 0.f) ? __logf(spx) : 0.f;
            float lnx = (snx > 0.f) ? __logf(snx) : 0.f;
            float lpy = (spy > 0.f) ? __logf(spy) : 0.f;
            float lny = (sny > 0.f) ? __logf(sny) : 0.f;
            v = g * ((lpx + lnx) + (lpy + lny));
        }
    }

    // warp reduce
    #pragma unroll
    for (int o = 16; o > 0; o >>= 1)
        v += __shfl_down_sync(0xFFFFFFFFu, v, o);

    __shared__ float sh[8];  // 256 threads = 8 warps
    int lane = threadIdx.x & 31;
    int wid  = threadIdx.x >> 5;
    if (lane == 0) sh[wid] = v;
    __syncthreads();

    if (wid == 0) {
        float bv = (lane < 8) ? sh[lane] : 0.f;
        #pragma unroll
        for (int o = 4; o > 0; o >>= 1)
            bv += __shfl_down_sync(0xFFFFFFFFu, bv, o);
        if (lane == 0)
            atomicAdd(out, bv);
    }
}

// ---------------------------------------------------------------------------
extern "C" void kernel_launch(void* const* d_in, const int* in_sizes, int n_in,
                              void* d_out, int out_size)
{
    const float* pos       = (const float*)d_in[0];   // [2 * num_pins]
    const int*   pin2net   = (const int*)d_in[1];     // [num_pins]
    const int*   net_mask  = (const int*)d_in[2];     // [num_nets] (bool as i32)
    const float* gamma_ptr = (const float*)d_in[3];   // scalar

    int num_pins = in_sizes[0] / 2;
    int num_nets = in_sizes[2];
    float* out = (float*)d_out;

    const int T = 256;

    int num_quads = num_pins / 4;
    if (num_quads > 0) {
        int pb = (num_quads + T - 1) / T;
        pins_kernel_vec4<<<pb, T>>>(
            (const float4*)pos,
            (const float4*)(pos + num_pins),
            (const int4*)pin2net,
            gamma_ptr, out, num_quads);
    } else {
        zero_out_kernel<<<1, 1>>>(out);
    }
    int tail_start = num_quads * 4;
    if (tail_start < num_pins) {
        int tcount = num_pins - tail_start;
        pins_kernel_tail<<<(tcount + T - 1) / T, T>>>(
            pos, pin2net, gamma_ptr, tail_start, num_pins);
    }

    int nb = (num_nets + T - 1) / T;
    nets_kernel<<<nb, T>>>(net_mask, gamma_ptr, out, num_nets);
}

// round 5
// speedup vs baseline: 1.6723x; 1.3958x over previous
#include <cuda_runtime.h>
#include <cuda_fp16.h>
#include <cuda_bf16.h>
#include <cstdint>

#define NUM_NETS_MAX 2000000

// Per-net accumulators packed as 2x f16x2 in 8 bytes:
//   .x = half2{exp(+x/g), exp(-x/g)}, .y = half2{exp(+y/g), exp(-y/g)}
// Zero at module load; nets_kernel re-zeroes after consuming each slot so
// every launch / graph replay starts from zeros.
__device__ uint2 g_net_sums_h[NUM_NETS_MAX];

// ---------------------------------------------------------------------------
// Kernel 1 (fallback only): zero scalar output.
// ---------------------------------------------------------------------------
__global__ void zero_out_kernel(float* __restrict__ out) {
    *out = 0.f;
}

// ---------------------------------------------------------------------------
// Kernel 2: per-pin exp + scatter-add. 4 pins per thread via vector loads,
// ONE red.global.add.noftz.v2.f16x2 (8 bytes) per pin.
// ---------------------------------------------------------------------------
__device__ __forceinline__ void scatter_pin(float sx, float sy, int net) {
    float epx = __expf(sx);
    float enx = __expf(-sx);
    float epy = __expf(sy);
    float eny = __expf(-sy);
    __half2 hx = __floats2half2_rn(epx, enx);
    __half2 hy = __floats2half2_rn(epy, eny);
    unsigned rx = *reinterpret_cast<unsigned*>(&hx);
    unsigned ry = *reinterpret_cast<unsigned*>(&hy);
    asm volatile("red.global.add.noftz.v2.f16x2 [%0], {%1, %2};"
                 :: "l"(&g_net_sums_h[net]), "r"(rx), "r"(ry)
                 : "memory");
}

__global__ void __launch_bounds__(256) pins_kernel_vec4(
    const float4* __restrict__ posx,
    const float4* __restrict__ posy,
    const int4*   __restrict__ pin2net,
    const float*  __restrict__ gamma_ptr,
    float* __restrict__ out,
    int num_quads)
{
    int q = blockIdx.x * blockDim.x + threadIdx.x;
    if (q == 0) *out = 0.f;   // nets_kernel (later in stream) accumulates into it
    if (q >= num_quads) return;

    float inv_g = 1.0f / (*gamma_ptr);

    float4 px = posx[q];
    float4 py = posy[q];
    int4   nn = pin2net[q];

    scatter_pin(px.x * inv_g, py.x * inv_g, nn.x);
    scatter_pin(px.y * inv_g, py.y * inv_g, nn.y);
    scatter_pin(px.z * inv_g, py.z * inv_g, nn.z);
    scatter_pin(px.w * inv_g, py.w * inv_g, nn.w);
}

// Tail kernel for num_pins % 4 != 0 (10M % 4 == 0, but stay correct).
__global__ void pins_kernel_tail(
    const float* __restrict__ pos,
    const int*   __restrict__ pin2net,
    const float* __restrict__ gamma_ptr,
    int start, int num_pins)
{
    int p = start + blockIdx.x * blockDim.x + threadIdx.x;
    if (p >= num_pins) return;
    float inv_g = 1.0f / (*gamma_ptr);
    scatter_pin(pos[p] * inv_g, pos[p + num_pins] * inv_g, pin2net[p]);
}

// ---------------------------------------------------------------------------
// Kernel 3: grid-stride streaming reducer. 4 nets per iteration (2x uint4
// scratch loads + int4 mask load + 2x uint4 zero stores). One block-reduce
// and one atomicAdd per BLOCK. net_mask is int32 on device.
// ---------------------------------------------------------------------------
__device__ __forceinline__ float net_term(unsigned rawx, unsigned rawy) {
    __half2 hx = *reinterpret_cast<__half2*>(&rawx);
    __half2 hy = *reinterpret_cast<__half2*>(&rawy);
    float spx = __low2float(hx);
    float snx = __high2float(hx);
    float spy = __low2float(hy);
    float sny = __high2float(hy);
    float lpx = (spx > 0.f) ? __logf(spx) : 0.f;
    float lnx = (snx > 0.f) ? __logf(snx) : 0.f;
    float lpy = (spy > 0.f) ? __logf(spy) : 0.f;
    float lny = (sny > 0.f) ? __logf(sny) : 0.f;
    return (lpx + lnx) + (lpy + lny);
}

__global__ void __launch_bounds__(256) nets_kernel_gs(
    const int4*  __restrict__ mask4,
    const float* __restrict__ gamma_ptr,
    float* __restrict__ out,
    int num_net_quads,   // num_nets / 4
    int tail_start,      // num_net_quads * 4
    int num_nets)
{
    uint4* sums4 = reinterpret_cast<uint4*>(g_net_sums_h);  // 2 nets per uint4
    const uint4 z4 = make_uint4(0u, 0u, 0u, 0u);

    int tid    = blockIdx.x * blockDim.x + threadIdx.x;
    int stride = gridDim.x * blockDim.x;

    float v = 0.f;

    for (int i = tid; i < num_net_quads; i += stride) {
        uint4 s01 = sums4[2 * i];       // nets 4i, 4i+1
        uint4 s23 = sums4[2 * i + 1];   // nets 4i+2, 4i+3
        int4  m   = mask4[i];
        sums4[2 * i]     = z4;          // reset for next launch
        sums4[2 * i + 1] = z4;

        if (m.x) v += net_term(s01.x, s01.y);
        if (m.y) v += net_term(s01.z, s01.w);
        if (m.z) v += net_term(s23.x, s23.y);
        if (m.w) v += net_term(s23.z, s23.w);
    }

    // scalar tail (num_nets % 4)
    const int* mask1 = reinterpret_cast<const int*>(mask4);
    for (int n = tail_start + tid; n < num_nets; n += stride) {
        uint2 raw = g_net_sums_h[n];
        g_net_sums_h[n] = make_uint2(0u, 0u);
        if (mask1[n]) v += net_term(raw.x, raw.y);
    }

    // block reduce (once per block)
    #pragma unroll
    for (int o = 16; o > 0; o >>= 1)
        v += __shfl_down_sync(0xFFFFFFFFu, v, o);

    __shared__ float sh[8];
    int lane = threadIdx.x & 31;
    int wid  = threadIdx.x >> 5;
    if (lane == 0) sh[wid] = v;
    __syncthreads();

    if (wid == 0) {
        float bv = (lane < 8) ? sh[lane] : 0.f;
        #pragma unroll
        for (int o = 4; o > 0; o >>= 1)
            bv += __shfl_down_sync(0xFFFFFFFFu, bv, o);
        if (lane == 0)
            atomicAdd(out, (*gamma_ptr) * bv);
    }
}

// ---------------------------------------------------------------------------
extern "C" void kernel_launch(void* const* d_in, const int* in_sizes, int n_in,
                              void* d_out, int out_size)
{
    const float* pos       = (const float*)d_in[0];   // [2 * num_pins]
    const int*   pin2net   = (const int*)d_in[1];     // [num_pins]
    const int*   net_mask  = (const int*)d_in[2];     // [num_nets] (bool as i32)
    const float* gamma_ptr = (const float*)d_in[3];   // scalar

    int num_pins = in_sizes[0] / 2;
    int num_nets = in_sizes[2];
    float* out = (float*)d_out;

    const int T = 256;

    int num_quads = num_pins / 4;
    if (num_quads > 0) {
        int pb = (num_quads + T - 1) / T;
        pins_kernel_vec4<<<pb, T>>>(
            (const float4*)pos,
            (const float4*)(pos + num_pins),
            (const int4*)pin2net,
            gamma_ptr, out, num_quads);
    } else {
        zero_out_kernel<<<1, 1>>>(out);
    }
    int tail_start_p = num_quads * 4;
    if (tail_start_p < num_pins) {
        int tcount = num_pins - tail_start_p;
        pins_kernel_tail<<<(tcount + T - 1) / T, T>>>(
            pos, pin2net, gamma_ptr, tail_start_p, num_pins);
    }

    int num_net_quads = num_nets / 4;
    int tail_start_n  = num_net_quads * 4;
    int nblocks = 1184;  // 8 blocks per SM on 148 SMs
    nets_kernel_gs<<<nblocks, T>>>(
        (const int4*)net_mask, gamma_ptr, out,
        num_net_quads, tail_start_n, num_nets);
}

// round 6
// speedup vs baseline: 1.7391x; 1.0400x over previous
#include <cuda_runtime.h>
#include <cuda_fp16.h>
#include <cuda_bf16.h>
#include <cstdint>

#define NUM_NETS_MAX 2000000

// Per-net accumulators packed as 2x f16x2 in 8 bytes:
//   .x = half2{exp(+x/g), exp(-x/g)}, .y = half2{exp(+y/g), exp(-y/g)}
// Zero at module load; nets kernel re-zeroes after consuming each slot so
// every launch / graph replay starts from zeros.
__device__ uint2 g_net_sums_h[NUM_NETS_MAX];

// ---------------------------------------------------------------------------
// Fallback: zero scalar output.
// ---------------------------------------------------------------------------
__global__ void zero_out_kernel(float* __restrict__ out) {
    *out = 0.f;
}

// ---------------------------------------------------------------------------
// Pins: per-pin exp + scatter-add. 8 pins per thread, wide loads batched
// up front for MLP; ONE red.global.add.noftz.v2.f16x2 (8B) per pin.
// ---------------------------------------------------------------------------
__device__ __forceinline__ void scatter_pin(float sx, float sy, int net) {
    float epx = __expf(sx);
    float enx = __expf(-sx);
    float epy = __expf(sy);
    float eny = __expf(-sy);
    __half2 hx = __floats2half2_rn(epx, enx);
    __half2 hy = __floats2half2_rn(epy, eny);
    unsigned rx = *reinterpret_cast<unsigned*>(&hx);
    unsigned ry = *reinterpret_cast<unsigned*>(&hy);
    asm volatile("red.global.add.noftz.v2.f16x2 [%0], {%1, %2};"
                 :: "l"(&g_net_sums_h[net]), "r"(rx), "r"(ry)
                 : "memory");
}

__global__ void __launch_bounds__(256) pins_kernel_vec8(
    const float4* __restrict__ posx,
    const float4* __restrict__ posy,
    const int4*   __restrict__ pin2net,
    const float*  __restrict__ gamma_ptr,
    float* __restrict__ out,
    int num_octs)   // num_pins / 8
{
    int t = blockIdx.x * blockDim.x + threadIdx.x;
    if (t == 0) *out = 0.f;   // nets kernel (later in stream) accumulates into it
    if (t >= num_octs) return;

    int q0 = 2 * t;
    int q1 = 2 * t + 1;

    // batch all 6 wide loads before any use
    float4 px0 = posx[q0];
    float4 px1 = posx[q1];
    float4 py0 = posy[q0];
    float4 py1 = posy[q1];
    int4   n0  = pin2net[q0];
    int4   n1  = pin2net[q1];

    float inv_g = 1.0f / (*gamma_ptr);

    scatter_pin(px0.x * inv_g, py0.x * inv_g, n0.x);
    scatter_pin(px0.y * inv_g, py0.y * inv_g, n0.y);
    scatter_pin(px0.z * inv_g, py0.z * inv_g, n0.z);
    scatter_pin(px0.w * inv_g, py0.w * inv_g, n0.w);
    scatter_pin(px1.x * inv_g, py1.x * inv_g, n1.x);
    scatter_pin(px1.y * inv_g, py1.y * inv_g, n1.y);
    scatter_pin(px1.z * inv_g, py1.z * inv_g, n1.z);
    scatter_pin(px1.w * inv_g, py1.w * inv_g, n1.w);
}

// Scalar tail for num_pins % 8 != 0 (10M % 8 == 0, but stay correct).
__global__ void pins_kernel_tail(
    const float* __restrict__ pos,
    const int*   __restrict__ pin2net,
    const float* __restrict__ gamma_ptr,
    int start, int num_pins)
{
    int p = start + blockIdx.x * blockDim.x + threadIdx.x;
    if (p >= num_pins) return;
    float inv_g = 1.0f / (*gamma_ptr);
    scatter_pin(pos[p] * inv_g, pos[p + num_pins] * inv_g, pin2net[p]);
}

// ---------------------------------------------------------------------------
// Nets: grid-stride streaming reducer, 8 nets per iteration.
// log(a)+log(b)+log(c)+log(d) = log(a*b*c*d); a..d are zero together
// (same pin set), so one prod>0 guard handles empty nets exactly.
// net_mask is int32 on device (JAX bool -> i32 materialization).
// ---------------------------------------------------------------------------
__device__ __forceinline__ float net_term(unsigned rawx, unsigned rawy) {
    __half2 hx = *reinterpret_cast<__half2*>(&rawx);
    __half2 hy = *reinterpret_cast<__half2*>(&rawy);
    float spx = __low2float(hx);
    float snx = __high2float(hx);
    float spy = __low2float(hy);
    float sny = __high2float(hy);
    float prod = (spx * snx) * (spy * sny);
    return (prod > 0.f) ? __logf(prod) : 0.f;
}

__global__ void __launch_bounds__(256) nets_kernel_gs8(
    const int4*  __restrict__ mask4,
    const float* __restrict__ gamma_ptr,
    float* __restrict__ out,
    int num_octs,        // num_nets / 8
    int tail_start,      // num_octs * 8
    int num_nets)
{
    uint4* sums4 = reinterpret_cast<uint4*>(g_net_sums_h);  // 2 nets per uint4
    const uint4 z4 = make_uint4(0u, 0u, 0u, 0u);

    int tid    = blockIdx.x * blockDim.x + threadIdx.x;
    int stride = gridDim.x * blockDim.x;

    float v = 0.f;

    for (int i = tid; i < num_octs; i += stride) {
        // batch loads: 4x 16B scratch + 2x 16B mask
        uint4 s0 = sums4[4 * i];        // nets 8i+0, 8i+1
        uint4 s1 = sums4[4 * i + 1];    // nets 8i+2, 8i+3
        uint4 s2 = sums4[4 * i + 2];    // nets 8i+4, 8i+5
        uint4 s3 = sums4[4 * i + 3];    // nets 8i+6, 8i+7
        int4  m0 = mask4[2 * i];
        int4  m1 = mask4[2 * i + 1];

        sums4[4 * i]     = z4;          // reset for next launch
        sums4[4 * i + 1] = z4;
        sums4[4 * i + 2] = z4;
        sums4[4 * i + 3] = z4;

        if (m0.x) v += net_term(s0.x, s0.y);
        if (m0.y) v += net_term(s0.z, s0.w);
        if (m0.z) v += net_term(s1.x, s1.y);
        if (m0.w) v += net_term(s1.z, s1.w);
        if (m1.x) v += net_term(s2.x, s2.y);
        if (m1.y) v += net_term(s2.z, s2.w);
        if (m1.z) v += net_term(s3.x, s3.y);
        if (m1.w) v += net_term(s3.z, s3.w);
    }

    // scalar tail (num_nets % 8)
    const int* mask1 = reinterpret_cast<const int*>(mask4);
    for (int n = tail_start + tid; n < num_nets; n += stride) {
        uint2 raw = g_net_sums_h[n];
        g_net_sums_h[n] = make_uint2(0u, 0u);
        if (mask1[n]) v += net_term(raw.x, raw.y);
    }

    // block reduce (once per block)
    #pragma unroll
    for (int o = 16; o > 0; o >>= 1)
        v += __shfl_down_sync(0xFFFFFFFFu, v, o);

    __shared__ float sh[8];
    int lane = threadIdx.x & 31;
    int wid  = threadIdx.x >> 5;
    if (lane == 0) sh[wid] = v;
    __syncthreads();

    if (wid == 0) {
        float bv = (lane < 8) ? sh[lane] : 0.f;
        #pragma unroll
        for (int o = 4; o > 0; o >>= 1)
            bv += __shfl_down_sync(0xFFFFFFFFu, bv, o);
        if (lane == 0)
            atomicAdd(out, (*gamma_ptr) * bv);
    }
}

// ---------------------------------------------------------------------------
extern "C" void kernel_launch(void* const* d_in, const int* in_sizes, int n_in,
                              void* d_out, int out_size)
{
    const float* pos       = (const float*)d_in[0];   // [2 * num_pins]
    const int*   pin2net   = (const int*)d_in[1];     // [num_pins]
    const int*   net_mask  = (const int*)d_in[2];     // [num_nets] (bool as i32)
    const float* gamma_ptr = (const float*)d_in[3];   // scalar

    int num_pins = in_sizes[0] / 2;
    int num_nets = in_sizes[2];
    float* out = (float*)d_out;

    const int T = 256;

    int num_pin_octs = num_pins / 8;
    if (num_pin_octs > 0) {
        int pb = (num_pin_octs + T - 1) / T;
        pins_kernel_vec8<<<pb, T>>>(
            (const float4*)pos,
            (const float4*)(pos + num_pins),
            (const int4*)pin2net,
            gamma_ptr, out, num_pin_octs);
    } else {
        zero_out_kernel<<<1, 1>>>(out);
    }
    int tail_start_p = num_pin_octs * 8;
    if (tail_start_p < num_pins) {
        int tcount = num_pins - tail_start_p;
        pins_kernel_tail<<<(tcount + T - 1) / T, T>>>(
            pos, pin2net, gamma_ptr, tail_start_p, num_pins);
    }

    int num_net_octs = num_nets / 8;
    int tail_start_n = num_net_octs * 8;
    int nblocks = 1184;  // 8 blocks per SM on 148 SMs
    nets_kernel_gs8<<<nblocks, T>>>(
        (const int4*)net_mask, gamma_ptr, out,
        num_net_octs, tail_start_n, num_nets);
}

// round 7
// speedup vs baseline: 1.7791x; 1.0230x over previous
#include <cuda_runtime.h>
#include <cuda_fp16.h>
#include <cuda_bf16.h>
#include <cstdint>

#define NUM_NETS_MAX 2000000

// Per-net accumulators packed as 2x f16x2 in 8 bytes:
//   .x = half2{exp(+x/g), exp(-x/g)}, .y = half2{exp(+y/g), exp(-y/g)}
// Zero at module load; nets kernel re-zeroes after consuming each slot so
// every launch / graph replay starts from zeros.
__device__ uint2 g_net_sums_h[NUM_NETS_MAX];

// ---------------------------------------------------------------------------
// Fallback: zero scalar output.
// ---------------------------------------------------------------------------
__global__ void zero_out_kernel(float* __restrict__ out) {
    *out = 0.f;
}

// ---------------------------------------------------------------------------
// Pins: per-pin exp + scatter-add. 8 pins per thread; ALL streaming loads use
// __ldcs (evict-first) so the 120MB read stream does not evict the 16MB
// L2-resident scratch that the REDG atomics hammer.
// ONE red.global.add.noftz.v2.f16x2 (8B) per pin.
// ---------------------------------------------------------------------------
__device__ __forceinline__ void scatter_pin(float sx, float sy, int net) {
    float epx = __expf(sx);
    float enx = __expf(-sx);
    float epy = __expf(sy);
    float eny = __expf(-sy);
    __half2 hx = __floats2half2_rn(epx, enx);
    __half2 hy = __floats2half2_rn(epy, eny);
    unsigned rx = *reinterpret_cast<unsigned*>(&hx);
    unsigned ry = *reinterpret_cast<unsigned*>(&hy);
    asm volatile("red.global.add.noftz.v2.f16x2 [%0], {%1, %2};"
                 :: "l"(&g_net_sums_h[net]), "r"(rx), "r"(ry)
                 : "memory");
}

__global__ void __launch_bounds__(256) pins_kernel_vec8(
    const float4* __restrict__ posx,
    const float4* __restrict__ posy,
    const int4*   __restrict__ pin2net,
    const float*  __restrict__ gamma_ptr,
    float* __restrict__ out,
    int num_octs)   // num_pins / 8
{
    int t = blockIdx.x * blockDim.x + threadIdx.x;
    if (t == 0) *out = 0.f;   // nets kernel (later in stream) accumulates into it
    if (t >= num_octs) return;

    int q0 = 2 * t;
    int q1 = 2 * t + 1;

    // batch all 6 wide loads before any use; evict-first (streaming)
    float4 px0 = __ldcs(&posx[q0]);
    float4 px1 = __ldcs(&posx[q1]);
    float4 py0 = __ldcs(&posy[q0]);
    float4 py1 = __ldcs(&posy[q1]);
    int4   n0  = __ldcs(&pin2net[q0]);
    int4   n1  = __ldcs(&pin2net[q1]);

    float inv_g = 1.0f / (*gamma_ptr);

    scatter_pin(px0.x * inv_g, py0.x * inv_g, n0.x);
    scatter_pin(px0.y * inv_g, py0.y * inv_g, n0.y);
    scatter_pin(px0.z * inv_g, py0.z * inv_g, n0.z);
    scatter_pin(px0.w * inv_g, py0.w * inv_g, n0.w);
    scatter_pin(px1.x * inv_g, py1.x * inv_g, n1.x);
    scatter_pin(px1.y * inv_g, py1.y * inv_g, n1.y);
    scatter_pin(px1.z * inv_g, py1.z * inv_g, n1.z);
    scatter_pin(px1.w * inv_g, py1.w * inv_g, n1.w);
}

// Scalar tail for num_pins % 8 != 0 (10M % 8 == 0, but stay correct).
__global__ void pins_kernel_tail(
    const float* __restrict__ pos,
    const int*   __restrict__ pin2net,
    const float* __restrict__ gamma_ptr,
    int start, int num_pins)
{
    int p = start + blockIdx.x * blockDim.x + threadIdx.x;
    if (p >= num_pins) return;
    float inv_g = 1.0f / (*gamma_ptr);
    scatter_pin(__ldcs(&pos[p]) * inv_g, __ldcs(&pos[p + num_pins]) * inv_g,
                __ldcs(&pin2net[p]));
}

// ---------------------------------------------------------------------------
// Nets: grid-stride streaming reducer, 8 nets per iteration.
// log(a)+log(b)+log(c)+log(d) = log(a*b*c*d); the four sums of a net are zero
// together (same pin set), so one prod>0 guard handles empty nets exactly.
// net_mask is int32 on device (JAX bool -> i32 materialization).
// ---------------------------------------------------------------------------
__device__ __forceinline__ float net_term(unsigned rawx, unsigned rawy) {
    __half2 hx = *reinterpret_cast<__half2*>(&rawx);
    __half2 hy = *reinterpret_cast<__half2*>(&rawy);
    float spx = __low2float(hx);
    float snx = __high2float(hx);
    float spy = __low2float(hy);
    float sny = __high2float(hy);
    float prod = (spx * snx) * (spy * sny);
    return (prod > 0.f) ? __logf(prod) : 0.f;
}

__global__ void __launch_bounds__(256) nets_kernel_gs8(
    const int4*  __restrict__ mask4,
    const float* __restrict__ gamma_ptr,
    float* __restrict__ out,
    int num_octs,        // num_nets / 8
    int tail_start,      // num_octs * 8
    int num_nets)
{
    uint4* sums4 = reinterpret_cast<uint4*>(g_net_sums_h);  // 2 nets per uint4
    const uint4 z4 = make_uint4(0u, 0u, 0u, 0u);

    int tid    = blockIdx.x * blockDim.x + threadIdx.x;
    int stride = gridDim.x * blockDim.x;

    float v = 0.f;

    for (int i = tid; i < num_octs; i += stride) {
        // batch loads: 4x 16B scratch (L2-hot) + 2x 16B mask (streaming)
        uint4 s0 = sums4[4 * i];        // nets 8i+0, 8i+1
        uint4 s1 = sums4[4 * i + 1];    // nets 8i+2, 8i+3
        uint4 s2 = sums4[4 * i + 2];    // nets 8i+4, 8i+5
        uint4 s3 = sums4[4 * i + 3];    // nets 8i+6, 8i+7
        int4  m0 = __ldcs(&mask4[2 * i]);
        int4  m1 = __ldcs(&mask4[2 * i + 1]);

        sums4[4 * i]     = z4;          // reset for next launch
        sums4[4 * i + 1] = z4;
        sums4[4 * i + 2] = z4;
        sums4[4 * i + 3] = z4;

        if (m0.x) v += net_term(s0.x, s0.y);
        if (m0.y) v += net_term(s0.z, s0.w);
        if (m0.z) v += net_term(s1.x, s1.y);
        if (m0.w) v += net_term(s1.z, s1.w);
        if (m1.x) v += net_term(s2.x, s2.y);
        if (m1.y) v += net_term(s2.z, s2.w);
        if (m1.z) v += net_term(s3.x, s3.y);
        if (m1.w) v += net_term(s3.z, s3.w);
    }

    // scalar tail (num_nets % 8)
    const int* mask1 = reinterpret_cast<const int*>(mask4);
    for (int n = tail_start + tid; n < num_nets; n += stride) {
        uint2 raw = g_net_sums_h[n];
        g_net_sums_h[n] = make_uint2(0u, 0u);
        if (mask1[n]) v += net_term(raw.x, raw.y);
    }

    // block reduce (once per block)
    #pragma unroll
    for (int o = 16; o > 0; o >>= 1)
        v += __shfl_down_sync(0xFFFFFFFFu, v, o);

    __shared__ float sh[8];
    int lane = threadIdx.x & 31;
    int wid  = threadIdx.x >> 5;
    if (lane == 0) sh[wid] = v;
    __syncthreads();

    if (wid == 0) {
        float bv = (lane < 8) ? sh[lane] : 0.f;
        #pragma unroll
        for (int o = 4; o > 0; o >>= 1)
            bv += __shfl_down_sync(0xFFFFFFFFu, bv, o);
        if (lane == 0)
            atomicAdd(out, (*gamma_ptr) * bv);
    }
}

// ---------------------------------------------------------------------------
extern "C" void kernel_launch(void* const* d_in, const int* in_sizes, int n_in,
                              void* d_out, int out_size)
{
    const float* pos       = (const float*)d_in[0];   // [2 * num_pins]
    const int*   pin2net   = (const int*)d_in[1];     // [num_pins]
    const int*   net_mask  = (const int*)d_in[2];     // [num_nets] (bool as i32)
    const float* gamma_ptr = (const float*)d_in[3];   // scalar

    int num_pins = in_sizes[0] / 2;
    int num_nets = in_sizes[2];
    float* out = (float*)d_out;

    const int T = 256;

    int num_pin_octs = num_pins / 8;
    if (num_pin_octs > 0) {
        int pb = (num_pin_octs + T - 1) / T;
        pins_kernel_vec8<<<pb, T>>>(
            (const float4*)pos,
            (const float4*)(pos + num_pins),
            (const int4*)pin2net,
            gamma_ptr, out, num_pin_octs);
    } else {
        zero_out_kernel<<<1, 1>>>(out);
    }
    int tail_start_p = num_pin_octs * 8;
    if (tail_start_p < num_pins) {
        int tcount = num_pins - tail_start_p;
        pins_kernel_tail<<<(tcount + T - 1) / T, T>>>(
            pos, pin2net, gamma_ptr, tail_start_p, num_pins);
    }

    int num_net_octs = num_nets / 8;
    int tail_start_n = num_net_octs * 8;
    int nblocks = 1184;  // 8 blocks per SM on 148 SMs
    nets_kernel_gs8<<<nblocks, T>>>(
        (const int4*)net_mask, gamma_ptr, out,
        num_net_octs, tail_start_n, num_nets);
}